// round 14
// baseline (speedup 1.0000x reference)
#include <cuda_runtime.h>

// Ray-marched volumetric sphere, 1024x1024 pixels, 2 pixels/thread.
// Fused 2-wide march, second-difference h recurrence, geometric light-
// attenuation factor, warp-coherent all-miss early-out.
// 2 px/thread (vs 4) halves register state -> ~2x occupancy for latency hiding.
// in[0] = scene (4 f32: cx, cy, cz, radius)
// in[1] = dirs  (1024*1024*3 f32, normalized)
// out   = pixels (1024*1024*3 f32)

#define LOG2E    1.4426950408889634f
#define K_LIGHT  (-1.2f * LOG2E)   // exp2 coeff: DENSITY*(SCAT+ABS) = 1.2
#define K_SIGMA  (-0.6f * LOG2E)   // exp2 coeff: SIGMA = 0.6

__device__ __forceinline__ float fsqrt_approx(float x) {
    float r; asm("sqrt.approx.f32 %0, %1;" : "=f"(r) : "f"(x)); return r;
}
__device__ __forceinline__ float fexp2_approx(float x) {
    float r; asm("ex2.approx.f32 %0, %1;" : "=f"(r) : "f"(x)); return r;
}

__global__ __launch_bounds__(128) void raymarch_kernel(
    const float* __restrict__ scene,
    const float2* __restrict__ dirs2,
    float2* __restrict__ out2,
    int nthreads)
{
    const int t = blockIdx.x * 128 + threadIdx.x;
    if (t >= nthreads) return;

    const float cx = __ldg(scene + 0);
    const float cy = __ldg(scene + 1);
    const float cz = __ldg(scene + 2);
    const float radius = __ldg(scene + 3);
    const float r2 = radius * radius;

    // RO = (0,0,3)
    const float ocx = -cx, ocy = -cy, ocz = 3.0f - cz;
    const float c0 = ocx * ocx + ocy * ocy + ocz * ocz - r2;

    // 2 pixels = 6 floats = 3 float2 (8B-aligned, coalesced)
    const float2 d0 = dirs2[3 * t + 0];
    const float2 d1 = dirs2[3 * t + 1];
    const float2 d2 = dirs2[3 * t + 2];

    const float rx[2] = {d0.x, d1.y};
    const float ry[2] = {d0.y, d2.x};
    const float rz[2] = {d1.x, d2.y};

    // ---- Cheap hit test (|rd| == 1, half-b form) ----
    float hbv[2], sqv[2], x2v[2];
    bool anyhit = false;
    #pragma unroll
    for (int j = 0; j < 2; j++) {
        const float hb = rx[j] * ocx + ry[j] * ocy + rz[j] * ocz;
        const float disc = hb * hb - c0;
        const float sq = fsqrt_approx(fmaxf(disc, 0.0f));
        const float x2 = sq - hb;
        hbv[j] = hb; sqv[j] = sq; x2v[j] = x2;
        anyhit |= (disc >= 0.0f) && (x2 >= 0.0f);
    }

    // Warp-coherent early-out: both pixels are background.
    if (!anyhit) {
        out2[3 * t + 0] = make_float2(0.572f, 0.772f);
        out2[3 * t + 1] = make_float2(0.921f, 0.572f);
        out2[3 * t + 2] = make_float2(0.772f, 0.921f);
        return;
    }

    // ---- Full march setup (miss lanes flow through with seg = 0) ----
    float h[2], u1[2], u2[2], P[2], G[2], acc[2], nsf[2], stp[2], sgl[2];
    float maxns = 0.0f;

    #pragma unroll
    for (int j = 0; j < 2; j++) {
        const float hb = hbv[j], sq = sqv[j], x2 = x2v[j];
        // Miss (disc<0 => sq=0, or x2<0) clamps to seg=0 -> ns=0, step=0
        // -> T=1, R=0: the background path, branch-free.
        const float t0 = fmaxf(-sq - hb, 0.0f);
        const float seg = fmaxf(x2 - t0, 0.0f);
        const float ns = ceilf(seg * 5.0f);            // seg / 0.2
        const float st = __fdividef(seg, fmaxf(ns, 1.0f));
        const float nf = fminf(ns, 12.0f);
        maxns = fmaxf(maxns, nf);

        // pc at k=0: oc + (x2 - 0.5*st)*rd; per-step delta = st*rd (backwards)
        const float ti = x2 - 0.5f * st;
        const float X0 = ocx + ti * rx[j];
        const float Y0 = ocy + ti * ry[j];
        const float Z0 = ocz + ti * rz[j];
        const float dx = st * rx[j], dy = st * ry[j], dz = st * rz[j];

        // h_k = r2 - pcx_k^2 - pcz_k^2 (quadratic in k): h += u1; u1 += u2
        const float dd = dx * dx + dz * dz;
        h[j]  = r2 - X0 * X0 - Z0 * Z0;
        u1[j] = 2.0f * (X0 * dx + Z0 * dz) - dd;
        u2[j] = -2.0f * dd;

        // e_k = exp2(K_LIGHT*sqrt(h_k)) * P_k,  P_k = P0 * G^k
        P[j] = fexp2_approx(-K_LIGHT * Y0);
        G[j] = fexp2_approx(K_LIGHT * dy);

        acc[j] = 0.0f; nsf[j] = nf; stp[j] = st; sgl[j] = seg;
    }

    // Fused march: 2 independent MUFU chains per iteration.
    // Sample points lie strictly inside the sphere => light ray always hits;
    // fabsf only guards fp noise at grazing rays (free modifier on MUFU).
    const int nit = (int)maxns;
    float kf = 0.0f;
    for (int it = 0; it < nit; it++, kf += 1.0f) {
        #pragma unroll
        for (int j = 0; j < 2; j++) {
            const float sq = fsqrt_approx(fabsf(h[j]));
            const float A = fexp2_approx(K_LIGHT * sq);
            if (kf < nsf[j]) acc[j] = fmaf(A, P[j], acc[j]);
            P[j] *= G[j];
            h[j] += u1[j]; u1[j] += u2[j];
        }
    }

    // Epilogue: step*ns == seg exactly (seg=0 for miss), so
    //   T = exp2(K_SIGMA*seg);  R = 0.6*step * T * exp2(K_SIGMA*step) * acc
    float T[2], R[2];
    #pragma unroll
    for (int j = 0; j < 2; j++) {
        T[j] = fexp2_approx(K_SIGMA * sgl[j]);
        R[j] = 0.6f * stp[j] * T[j] * fexp2_approx(K_SIGMA * stp[j]) * acc[j];
    }

    // color = BG*T + LIGHT*R; BG=(0.572,0.772,0.921), LIGHT=(1.3,0.3,0.9)
    float2 o0, o1, o2;
    o0.x = 0.572f * T[0] + 1.3f * R[0];
    o0.y = 0.772f * T[0] + 0.3f * R[0];
    o1.x = 0.921f * T[0] + 0.9f * R[0];
    o1.y = 0.572f * T[1] + 1.3f * R[1];
    o2.x = 0.772f * T[1] + 0.3f * R[1];
    o2.y = 0.921f * T[1] + 0.9f * R[1];

    out2[3 * t + 0] = o0;
    out2[3 * t + 1] = o1;
    out2[3 * t + 2] = o2;
}

extern "C" void kernel_launch(void* const* d_in, const int* in_sizes, int n_in,
                              void* d_out, int out_size) {
    const float* scene = (const float*)d_in[0];
    const float2* dirs2 = (const float2*)d_in[1];
    float2* out2 = (float2*)d_out;
    const int npix = in_sizes[1] / 3;
    const int nthreads = npix / 2;          // 2 pixels per thread
    const int threads = 128;
    const int blocks = (nthreads + threads - 1) / threads;
    raymarch_kernel<<<blocks, threads>>>(scene, dirs2, out2, nthreads);
}

// round 17
// speedup vs baseline: 1.0239x; 1.0239x over previous
#include <cuda_runtime.h>

// Ray-marched volumetric sphere, 1024x1024 pixels, 4 pixels/thread.
// Fused 4-wide march, second-difference h recurrence, geometric light-
// attenuation factor, warp-coherent all-miss early-out with a SQRT-FREE
// exact hit test (x2>=0 <=> hb<=0 when c0>0; constant fold).
// in[0] = scene (4 f32: cx, cy, cz, radius)
// in[1] = dirs  (1024*1024*3 f32, normalized)
// out   = pixels (1024*1024*3 f32)

#define LOG2E    1.4426950408889634f
#define K_LIGHT  (-1.2f * LOG2E)   // exp2 coeff: DENSITY*(SCAT+ABS) = 1.2
#define K_SIGMA  (-0.6f * LOG2E)   // exp2 coeff: SIGMA = 0.6

__device__ __forceinline__ float fsqrt_approx(float x) {
    float r; asm("sqrt.approx.f32 %0, %1;" : "=f"(r) : "f"(x)); return r;
}
__device__ __forceinline__ float fexp2_approx(float x) {
    float r; asm("ex2.approx.f32 %0, %1;" : "=f"(r) : "f"(x)); return r;
}

__global__ __launch_bounds__(128) void raymarch_kernel(
    const float* __restrict__ scene,
    const float4* __restrict__ dirs4,
    float4* __restrict__ out4,
    int nthreads)
{
    const int t = blockIdx.x * 128 + threadIdx.x;
    if (t >= nthreads) return;

    const float cx = __ldg(scene + 0);
    const float cy = __ldg(scene + 1);
    const float cz = __ldg(scene + 2);
    const float radius = __ldg(scene + 3);
    const float r2 = radius * radius;

    // RO = (0,0,3)
    const float ocx = -cx, ocy = -cy, ocz = 3.0f - cz;
    const float c0 = ocx * ocx + ocy * ocy + ocz * ocz - r2;
    const bool inside = (c0 <= 0.0f);   // camera inside sphere (scene const)

    const float4 d0 = dirs4[3 * t + 0];
    const float4 d1 = dirs4[3 * t + 1];
    const float4 d2 = dirs4[3 * t + 2];

    const float rx[4] = {d0.x, d0.w, d1.z, d2.y};
    const float ry[4] = {d0.y, d1.x, d1.w, d2.z};
    const float rz[4] = {d0.z, d1.y, d2.x, d2.w};

    // ---- Sqrt-free exact hit test (|rd| == 1, half-b form) ----
    // x2 = sqrt(disc) - hb >= 0  <=>  hb <= 0  OR  disc >= hb^2 (= c0 <= 0).
    float hbv[4], dscv[4];
    bool anyhit = false;
    #pragma unroll
    for (int j = 0; j < 4; j++) {
        const float hb = rx[j] * ocx + ry[j] * ocy + rz[j] * ocz;
        const float disc = hb * hb - c0;
        hbv[j] = hb; dscv[j] = disc;
        anyhit |= (disc >= 0.0f) && ((hb <= 0.0f) || inside);
    }

    // Warp-coherent early-out: all 4 pixels are background.
    if (!anyhit) {
        out4[3 * t + 0] = make_float4(0.572f, 0.772f, 0.921f, 0.572f);
        out4[3 * t + 1] = make_float4(0.772f, 0.921f, 0.572f, 0.772f);
        out4[3 * t + 2] = make_float4(0.921f, 0.572f, 0.772f, 0.921f);
        return;
    }

    // ---- Full march setup (miss lanes flow through with seg = 0) ----
    float h[4], u1[4], u2[4], P[4], G[4], acc[4], nsf[4], stp[4], sgl[4];
    float maxns = 0.0f;

    #pragma unroll
    for (int j = 0; j < 4; j++) {
        const float hb = hbv[j];
        const float sq = fsqrt_approx(fmaxf(dscv[j], 0.0f));
        const float x2 = sq - hb;
        // Miss (disc<0 => sq=0, or x2<0) clamps to seg=0 -> ns=0, step=0
        // -> T=1, R=0: the background path, branch-free.
        const float t0 = fmaxf(-sq - hb, 0.0f);
        const float seg = fmaxf(x2 - t0, 0.0f);
        const float ns = ceilf(seg * 5.0f);            // seg / 0.2
        const float st = __fdividef(seg, fmaxf(ns, 1.0f));
        const float nf = fminf(ns, 12.0f);
        maxns = fmaxf(maxns, nf);

        // pc at k=0: oc + (x2 - 0.5*st)*rd; per-step delta = st*rd (backwards)
        const float ti = x2 - 0.5f * st;
        const float X0 = ocx + ti * rx[j];
        const float Y0 = ocy + ti * ry[j];
        const float Z0 = ocz + ti * rz[j];
        const float dx = st * rx[j], dy = st * ry[j], dz = st * rz[j];

        // h_k = r2 - pcx_k^2 - pcz_k^2 (quadratic in k): h += u1; u1 += u2
        const float dd = dx * dx + dz * dz;
        h[j]  = r2 - X0 * X0 - Z0 * Z0;
        u1[j] = 2.0f * (X0 * dx + Z0 * dz) - dd;
        u2[j] = -2.0f * dd;

        // e_k = exp2(K_LIGHT*sqrt(h_k)) * P_k,  P_k = P0 * G^k
        //   P0 = exp2(-K_LIGHT * pcy_0),  G = exp2(K_LIGHT * dy)
        P[j] = fexp2_approx(-K_LIGHT * Y0);
        G[j] = fexp2_approx(K_LIGHT * dy);

        acc[j] = 0.0f; nsf[j] = nf; stp[j] = st; sgl[j] = seg;
    }

    // Fused march: 4 independent MUFU chains per iteration.
    // Sample points lie strictly inside the sphere => light ray always hits;
    // fabsf only guards fp noise at grazing rays (free modifier on MUFU).
    const int nit = (int)maxns;
    float kf = 0.0f;
    for (int it = 0; it < nit; it++, kf += 1.0f) {
        #pragma unroll
        for (int j = 0; j < 4; j++) {
            const float sq = fsqrt_approx(fabsf(h[j]));
            const float A = fexp2_approx(K_LIGHT * sq);
            if (kf < nsf[j]) acc[j] = fmaf(A, P[j], acc[j]);
            P[j] *= G[j];
            h[j] += u1[j]; u1[j] += u2[j];
        }
    }

    // Epilogue: step*ns == seg exactly (seg=0 for miss), so
    //   T = exp2(K_SIGMA*seg);  R = 0.6*step * T * exp2(K_SIGMA*step) * acc
    float T[4], R[4];
    #pragma unroll
    for (int j = 0; j < 4; j++) {
        T[j] = fexp2_approx(K_SIGMA * sgl[j]);
        R[j] = 0.6f * stp[j] * T[j] * fexp2_approx(K_SIGMA * stp[j]) * acc[j];
    }

    // color = BG*T + LIGHT*R; BG=(0.572,0.772,0.921), LIGHT=(1.3,0.3,0.9)
    float4 o0, o1, o2;
    o0.x = 0.572f * T[0] + 1.3f * R[0];
    o0.y = 0.772f * T[0] + 0.3f * R[0];
    o0.z = 0.921f * T[0] + 0.9f * R[0];
    o0.w = 0.572f * T[1] + 1.3f * R[1];
    o1.x = 0.772f * T[1] + 0.3f * R[1];
    o1.y = 0.921f * T[1] + 0.9f * R[1];
    o1.z = 0.572f * T[2] + 1.3f * R[2];
    o1.w = 0.772f * T[2] + 0.3f * R[2];
    o2.x = 0.921f * T[2] + 0.9f * R[2];
    o2.y = 0.572f * T[3] + 1.3f * R[3];
    o2.z = 0.772f * T[3] + 0.3f * R[3];
    o2.w = 0.921f * T[3] + 0.9f * R[3];

    out4[3 * t + 0] = o0;
    out4[3 * t + 1] = o1;
    out4[3 * t + 2] = o2;
}

extern "C" void kernel_launch(void* const* d_in, const int* in_sizes, int n_in,
                              void* d_out, int out_size) {
    const float* scene = (const float*)d_in[0];
    const float4* dirs4 = (const float4*)d_in[1];
    float4* out4 = (float4*)d_out;
    const int npix = in_sizes[1] / 3;
    const int nthreads = npix / 4;
    const int threads = 128;
    const int blocks = (nthreads + threads - 1) / threads;
    raymarch_kernel<<<blocks, threads>>>(scene, dirs4, out4, nthreads);
}